// round 1
// baseline (speedup 1.0000x reference)
#include <cuda_runtime.h>
#include <math.h>

#define Bc 16
#define Lc 2048
#define Dc 192
#define Hc 4
#define Kc 12

// ---------------- scratch (no allocations allowed) ----------------
__device__ float g_xn [(size_t)Bc*Lc*Dc];       // xn1 then xn2 (reused)
__device__ float g_q  [(size_t)Bc*Hc*Lc*Kc];    // [B,H,L,K]
__device__ float g_k  [(size_t)Bc*Hc*Lc*Kc];
__device__ float g_v  [(size_t)Bc*Hc*Lc*Kc];
__device__ float g_ctx[(size_t)Bc*Lc*Hc*Kc];    // [B,L,H,K]
__device__ float g_y1 [(size_t)Bc*Lc*Dc];       // x + MHA
__device__ float g_h  [(size_t)Bc*Lc*Dc];       // relu(conv1), zero-padded rows 0, L-1

// ---------------- LayerNorm: one warp per row ----------------
template<int SRC>
__global__ void ln_kernel(const float* __restrict__ xin,
                          const float* __restrict__ gamma,
                          const float* __restrict__ beta)
{
    int gw   = (blockIdx.x * blockDim.x + threadIdx.x) >> 5;
    int lane = threadIdx.x & 31;
    if (gw >= Bc * Lc) return;
    const float* row = (SRC == 0 ? xin : g_y1) + (size_t)gw * Dc;
    float v[6];
    float s = 0.f;
#pragma unroll
    for (int i = 0; i < 6; i++) { v[i] = row[lane + 32*i]; s += v[i]; }
#pragma unroll
    for (int o = 16; o; o >>= 1) s += __shfl_xor_sync(0xffffffffu, s, o);
    float mean = s * (1.f/192.f);
    float vs = 0.f;
#pragma unroll
    for (int i = 0; i < 6; i++) { float d = v[i] - mean; vs += d*d; }
#pragma unroll
    for (int o = 16; o; o >>= 1) vs += __shfl_xor_sync(0xffffffffu, vs, o);
    float inv = rsqrtf(vs * (1.f/192.f) + 1e-3f);
#pragma unroll
    for (int i = 0; i < 6; i++) {
        int c = lane + 32*i;
        g_xn[(size_t)gw * Dc + c] = (v[i] - mean) * inv * gamma[c] + beta[c];
    }
}

// ---------------- QKV projection: block = 16 rows x 144 outputs ----------------
__global__ void qkv_kernel(const float* __restrict__ wq, const float* __restrict__ bq,
                           const float* __restrict__ wk, const float* __restrict__ bk,
                           const float* __restrict__ wv, const float* __restrict__ bv)
{
    __shared__ float sx[16 * Dc];
    int rowbase = blockIdx.x * 16;
    int tid = threadIdx.x;                  // 144 threads
    for (int idx = tid; idx < 16 * Dc; idx += 144)
        sx[idx] = g_xn[(size_t)rowbase * Dc + idx];
    __syncthreads();

    int s   = tid / 48;                     // 0=q 1=k 2=v
    int j48 = tid % 48;
    const float* W  = (s == 0) ? wq : (s == 1) ? wk : wv;
    const float* Bp = (s == 0) ? bq : (s == 1) ? bk : bv;
    float acc[16];
#pragma unroll
    for (int r = 0; r < 16; r++) acc[r] = 0.f;

#pragma unroll 4
    for (int d = 0; d < Dc; d++) {
        float w = W[d * 48 + j48];
#pragma unroll
        for (int r = 0; r < 16; r++) acc[r] += sx[r * Dc + d] * w;
    }
    int h = j48 / Kc, kk = j48 % Kc;
    float bias = Bp[j48];
    float* O = (s == 0) ? g_q : (s == 1) ? g_k : g_v;
#pragma unroll
    for (int r = 0; r < 16; r++) {
        int row = rowbase + r;
        int bb = row / Lc, l = row % Lc;
        O[(((size_t)bb * Hc + h) * Lc + l) * Kc + kk] = acc[r] + bias;
    }
}

// ---------------- causal attention (flash-style, no-max softmax) ----------------
// block: 128 threads, 256 queries (2 per thread). K/V tiles of 128 keys in SMEM.
// MODE 0: no masks needed. MODE 1: mask only q1. MODE 2: skip q1, mask q2.
template<int MODE>
__device__ __forceinline__ void attn_tile(const float4* __restrict__ sk,
                                          const float4* __restrict__ sv,
                                          int mbase, int l1, int l2,
                                          const float* q1, const float* q2,
                                          float* o1, float* o2,
                                          float& d1, float& d2)
{
#pragma unroll 4
    for (int mm = 0; mm < 128; mm++) {
        float4 ka = sk[3*mm], kb = sk[3*mm+1], kc = sk[3*mm+2];
        int m = mbase + mm;
        float p1 = 0.f;
        if (MODE < 2) {
            float s1 = q1[0]*ka.x + q1[1]*ka.y + q1[2]*ka.z + q1[3]*ka.w
                     + q1[4]*kb.x + q1[5]*kb.y + q1[6]*kb.z + q1[7]*kb.w
                     + q1[8]*kc.x + q1[9]*kc.y + q1[10]*kc.z + q1[11]*kc.w;
            p1 = (MODE == 0) ? __expf(s1) : ((m <= l1) ? __expf(s1) : 0.f);
        }
        float s2 = q2[0]*ka.x + q2[1]*ka.y + q2[2]*ka.z + q2[3]*ka.w
                 + q2[4]*kb.x + q2[5]*kb.y + q2[6]*kb.z + q2[7]*kb.w
                 + q2[8]*kc.x + q2[9]*kc.y + q2[10]*kc.z + q2[11]*kc.w;
        float p2 = (MODE == 2) ? ((m <= l2) ? __expf(s2) : 0.f) : __expf(s2);
        d1 += p1; d2 += p2;
        float4 va = sv[3*mm], vb = sv[3*mm+1], vc = sv[3*mm+2];
        if (MODE < 2) {
            o1[0] += p1*va.x; o1[1] += p1*va.y; o1[2]  += p1*va.z; o1[3]  += p1*va.w;
            o1[4] += p1*vb.x; o1[5] += p1*vb.y; o1[6]  += p1*vb.z; o1[7]  += p1*vb.w;
            o1[8] += p1*vc.x; o1[9] += p1*vc.y; o1[10] += p1*vc.z; o1[11] += p1*vc.w;
        }
        o2[0] += p2*va.x; o2[1] += p2*va.y; o2[2]  += p2*va.z; o2[3]  += p2*va.w;
        o2[4] += p2*vb.x; o2[5] += p2*vb.y; o2[6]  += p2*vb.z; o2[7]  += p2*vb.w;
        o2[8] += p2*vc.x; o2[9] += p2*vc.y; o2[10] += p2*vc.z; o2[11] += p2*vc.w;
    }
}

__global__ void attn_kernel()
{
    __shared__ float4 sk[128 * 3];
    __shared__ float4 sv[128 * 3];
    int qt = blockIdx.x, h = blockIdx.y, bb = blockIdx.z;
    int t = threadIdx.x;
    int l1 = qt * 256 + t;
    int l2 = l1 + 128;

    size_t head = ((size_t)bb * Hc + h) * Lc * Kc;
    const float4* qb = (const float4*)(g_q + head);
    const float*  kb = g_k + head;
    const float*  vb = g_v + head;

    const float scale = 0.28867513459481287f;   // 1/sqrt(12)
    float q1[12], q2[12];
    {
        float4 a = qb[3*l1], b = qb[3*l1+1], c = qb[3*l1+2];
        q1[0]=a.x*scale; q1[1]=a.y*scale; q1[2]=a.z*scale; q1[3]=a.w*scale;
        q1[4]=b.x*scale; q1[5]=b.y*scale; q1[6]=b.z*scale; q1[7]=b.w*scale;
        q1[8]=c.x*scale; q1[9]=c.y*scale; q1[10]=c.z*scale; q1[11]=c.w*scale;
        a = qb[3*l2]; b = qb[3*l2+1]; c = qb[3*l2+2];
        q2[0]=a.x*scale; q2[1]=a.y*scale; q2[2]=a.z*scale; q2[3]=a.w*scale;
        q2[4]=b.x*scale; q2[5]=b.y*scale; q2[6]=b.z*scale; q2[7]=b.w*scale;
        q2[8]=c.x*scale; q2[9]=c.y*scale; q2[10]=c.z*scale; q2[11]=c.w*scale;
    }
    float o1[12], o2[12];
#pragma unroll
    for (int i = 0; i < 12; i++) { o1[i] = 0.f; o2[i] = 0.f; }
    float d1 = 0.f, d2 = 0.f;

    int full = 2 * qt;   // tiles with no masking at all
    for (int kt = 0; kt <= full + 1; kt++) {
        __syncthreads();
        const float4* ks = (const float4*)(kb + (size_t)kt * 128 * Kc);
        const float4* vs = (const float4*)(vb + (size_t)kt * 128 * Kc);
        for (int i = t; i < 128 * 3; i += 128) { sk[i] = ks[i]; sv[i] = vs[i]; }
        __syncthreads();
        int mbase = kt * 128;
        if      (kt <  full) attn_tile<0>(sk, sv, mbase, l1, l2, q1, q2, o1, o2, d1, d2);
        else if (kt == full) attn_tile<1>(sk, sv, mbase, l1, l2, q1, q2, o1, o2, d1, d2);
        else                 attn_tile<2>(sk, sv, mbase, l1, l2, q1, q2, o1, o2, d1, d2);
    }

    float i1 = 1.f / d1, i2 = 1.f / d2;
    float4* out1 = (float4*)(g_ctx + (((size_t)bb * Lc + l1) * Hc + h) * Kc);
    float4* out2 = (float4*)(g_ctx + (((size_t)bb * Lc + l2) * Hc + h) * Kc);
    out1[0] = make_float4(o1[0]*i1, o1[1]*i1, o1[2]*i1,  o1[3]*i1);
    out1[1] = make_float4(o1[4]*i1, o1[5]*i1, o1[6]*i1,  o1[7]*i1);
    out1[2] = make_float4(o1[8]*i1, o1[9]*i1, o1[10]*i1, o1[11]*i1);
    out2[0] = make_float4(o2[0]*i2, o2[1]*i2, o2[2]*i2,  o2[3]*i2);
    out2[1] = make_float4(o2[4]*i2, o2[5]*i2, o2[6]*i2,  o2[7]*i2);
    out2[2] = make_float4(o2[8]*i2, o2[9]*i2, o2[10]*i2, o2[11]*i2);
}

// ---------------- output projection + residual ----------------
__global__ void proj_kernel(const float* __restrict__ x,
                            const float* __restrict__ wo,
                            const float* __restrict__ bo)
{
    __shared__ float sc[16 * 48];
    int rowbase = blockIdx.x * 16;
    int j = threadIdx.x;                    // 192 threads = output column
    for (int idx = j; idx < 16 * 48; idx += 192)
        sc[idx] = g_ctx[(size_t)rowbase * 48 + idx];
    __syncthreads();
    float acc[16];
#pragma unroll
    for (int r = 0; r < 16; r++) acc[r] = 0.f;
#pragma unroll 4
    for (int i = 0; i < 48; i++) {
        float w = wo[i * Dc + j];
#pragma unroll
        for (int r = 0; r < 16; r++) acc[r] += sc[r * 48 + i] * w;
    }
    float bias = bo[j];
#pragma unroll
    for (int r = 0; r < 16; r++) {
        size_t o = (size_t)(rowbase + r) * Dc + j;
        g_y1[o] = acc[r] + bias + x[o];
    }
}

// ---------------- conv1d (kernel 3, VALID) as GEMM, 16 rows x 2 cols / thread ----
// MODE 0: src=g_xn, dst=g_h, relu, zero on rows 0 and L-1.
// MODE 1: src=g_h, dst=out (final), add g_y1, zero conv part on rows 0 and L-1.
template<int MODE>
__global__ void conv_kernel(const float* __restrict__ W,
                            const float* __restrict__ bias,
                            float* __restrict__ out)
{
    __shared__ float sx[18 * Dc];
    int l0 = blockIdx.x * 16;
    int bb = blockIdx.y;
    int tid = threadIdx.x;                  // 96 threads
    const float* src = (MODE == 0) ? g_xn : g_h;

    for (int idx = tid; idx < 18 * Dc; idx += 96) {
        int rr = idx / Dc, c = idx % Dc;
        int l = l0 - 1 + rr;
        l = l < 0 ? 0 : (l > Lc - 1 ? Lc - 1 : l);
        sx[idx] = src[((size_t)bb * Lc + l) * Dc + c];
    }
    __syncthreads();

    int j = tid * 2;
    float a0[16], a1[16];
#pragma unroll
    for (int r = 0; r < 16; r++) { a0[r] = 0.f; a1[r] = 0.f; }

    for (int c = 0; c < Dc; c++) {
        float in[18];
#pragma unroll
        for (int rr = 0; rr < 18; rr++) in[rr] = sx[rr * Dc + c];
#pragma unroll
        for (int tt = 0; tt < 3; tt++) {
            float2 w = *(const float2*)(W + ((size_t)(tt * Dc + c)) * Dc + j);
#pragma unroll
            for (int r = 0; r < 16; r++) {
                a0[r] += in[r + tt] * w.x;
                a1[r] += in[r + tt] * w.y;
            }
        }
    }

    float b0 = bias[j], b1 = bias[j + 1];
    float* dst = (MODE == 0) ? g_h : out;
#pragma unroll
    for (int r = 0; r < 16; r++) {
        int l = l0 + r;
        bool interior = (l >= 1) && (l <= Lc - 2);
        size_t o = ((size_t)bb * Lc + l) * Dc + j;
        float v0 = a0[r] + b0, v1 = a1[r] + b1;
        float2 res;
        if (MODE == 0) {
            res.x = interior ? fmaxf(v0, 0.f) : 0.f;
            res.y = interior ? fmaxf(v1, 0.f) : 0.f;
        } else {
            float2 y = *(const float2*)(g_y1 + o);
            res.x = y.x + (interior ? v0 : 0.f);
            res.y = y.y + (interior ? v1 : 0.f);
        }
        *(float2*)(dst + o) = res;
    }
}

// ---------------- launcher ----------------
extern "C" void kernel_launch(void* const* d_in, const int* in_sizes, int n_in,
                              void* d_out, int out_size)
{
    const float* x     = (const float*)d_in[0];
    const float* ln1_g = (const float*)d_in[1];
    const float* ln1_b = (const float*)d_in[2];
    const float* wq    = (const float*)d_in[3];
    const float* bq    = (const float*)d_in[4];
    const float* wk    = (const float*)d_in[5];
    const float* bk    = (const float*)d_in[6];
    const float* wv    = (const float*)d_in[7];
    const float* bv    = (const float*)d_in[8];
    const float* wo    = (const float*)d_in[9];
    const float* bo    = (const float*)d_in[10];
    const float* ln2_g = (const float*)d_in[11];
    const float* ln2_b = (const float*)d_in[12];
    const float* c1_w  = (const float*)d_in[13];
    const float* c1_b  = (const float*)d_in[14];
    const float* c2_w  = (const float*)d_in[15];
    const float* c2_b  = (const float*)d_in[16];
    float* outp = (float*)d_out;

    ln_kernel<0><<<(Bc*Lc)/8, 256>>>(x, ln1_g, ln1_b);
    qkv_kernel<<<(Bc*Lc)/16, 144>>>(wq, bq, wk, bk, wv, bv);
    attn_kernel<<<dim3(Lc/256, Hc, Bc), 128>>>();
    proj_kernel<<<(Bc*Lc)/16, 192>>>(x, wo, bo);
    ln_kernel<1><<<(Bc*Lc)/8, 256>>>(x, ln2_g, ln2_b);
    conv_kernel<0><<<dim3(Lc/16, Bc), 96>>>(c1_w, c1_b, outp);
    conv_kernel<1><<<dim3(Lc/16, Bc), 96>>>(c2_w, c2_b, outp);
}